// round 11
// baseline (speedup 1.0000x reference)
#include <cuda_runtime.h>
#include <cuda_fp16.h>
#include <math.h>
#include <stdint.h>

#define BB 128
#define NN 256
#define DD 512
#define OO 512
#define MROWS (BB * NN)   // 32768

// ---------------------------------------------------------------------------
// Scratch (no cudaMalloc allowed)
// ---------------------------------------------------------------------------
__device__ __half g_x16[(size_t)MROWS * DD];       // block1: fp16(Obs); block3: fp16(h1+h2)
__device__ __half g_h1[(size_t)MROWS * OO];        // fp16 GEMM1 output
__device__ __half g_h2[(size_t)MROWS * OO];        // fp16 GEMM2 output
__device__ __half g_wg[3 * (size_t)DD * OO];       // (g∘W)^T per layer: [N][K] fp16
__device__ float  g_mean[MROWS];
__device__ float  g_rstd[MROWS];
__device__ float  g_S[3 * OO];
__device__ float  g_T[3 * OO];
__device__ float  g_Sp[3 * 64 * OO];
__device__ float  g_Tp[3 * 64 * OO];

// ---------------------------------------------------------------------------
// Helpers (sm_80-era PTX only — must assemble under compute_103)
// ---------------------------------------------------------------------------
__device__ __forceinline__ uint32_t smem_to_u32(const void* p) {
    uint32_t a;
    asm("{ .reg .u64 t; cvta.to.shared.u64 t, %1; cvt.u32.u64 %0, t; }"
        : "=r"(a) : "l"(p));
    return a;
}
__device__ __forceinline__ void cp16(uint32_t dst, const void* src) {
    asm volatile("cp.async.cg.shared.global [%0], [%1], 16;"
                 :: "r"(dst), "l"(src) : "memory");
}
__device__ __forceinline__ void ldm_x4(uint32_t* r, uint32_t addr) {
    asm volatile("ldmatrix.sync.aligned.m8n8.x4.shared.b16 {%0,%1,%2,%3}, [%4];"
                 : "=r"(r[0]), "=r"(r[1]), "=r"(r[2]), "=r"(r[3]) : "r"(addr));
}
__device__ __forceinline__ void mma_fp16(float* c, const uint32_t* a,
                                         uint32_t b0, uint32_t b1) {
    asm volatile(
        "mma.sync.aligned.m16n8k16.row.col.f32.f16.f16.f32 "
        "{%0,%1,%2,%3}, {%4,%5,%6,%7}, {%8,%9}, {%0,%1,%2,%3};"
        : "+f"(c[0]), "+f"(c[1]), "+f"(c[2]), "+f"(c[3])
        : "r"(a[0]), "r"(a[1]), "r"(a[2]), "r"(a[3]), "r"(b0), "r"(b1));
}

// Block-wide (128 threads) mean/rstd reduction.
__device__ __forceinline__ void row_stats_finish(float s, float ss, int row,
                                                 float* mean, float* rstd, int tid) {
    #pragma unroll
    for (int o = 16; o > 0; o >>= 1) {
        s  += __shfl_xor_sync(0xFFFFFFFFu, s,  o);
        ss += __shfl_xor_sync(0xFFFFFFFFu, ss, o);
    }
    __shared__ float sh_s[4], sh_ss[4];
    const int w = tid >> 5;
    if ((tid & 31) == 0) { sh_s[w] = s; sh_ss[w] = ss; }
    __syncthreads();
    if (tid == 0) {
        s  = sh_s[0] + sh_s[1] + sh_s[2] + sh_s[3];
        ss = sh_ss[0] + sh_ss[1] + sh_ss[2] + sh_ss[3];
        const float mn  = s * (1.0f / DD);
        const float var = ss * (1.0f / DD) - mn * mn;
        mean[row] = mn;
        rstd[row] = rsqrtf(var + 1e-5f);
    }
}

// ---------------------------------------------------------------------------
// Block 1 stats: read fp32 x, write fp16(x) + row mean/rstd (stats from fp32).
// ---------------------------------------------------------------------------
__global__ void stats32_kernel(const float* __restrict__ x,
                               __half* __restrict__ x16,
                               float* __restrict__ mean,
                               float* __restrict__ rstd) {
    const int row = blockIdx.x;
    const int tid = threadIdx.x;
    float4 v = reinterpret_cast<const float4*>(x + (size_t)row * DD)[tid];

    __half2* p = reinterpret_cast<__half2*>(x16 + (size_t)row * DD);
    p[tid * 2]     = __halves2half2(__float2half_rn(v.x), __float2half_rn(v.y));
    p[tid * 2 + 1] = __halves2half2(__float2half_rn(v.z), __float2half_rn(v.w));

    float s  = v.x + v.y + v.z + v.w;
    float ss = v.x * v.x + v.y * v.y + v.z * v.z + v.w * v.w;
    row_stats_finish(s, ss, row, mean, rstd, tid);
}

// ---------------------------------------------------------------------------
// Stats from fp16 input (block 2: b==nullptr). Block 3 (b!=nullptr):
// forms fp16(a+b), writes to sum_out, stats from the rounded sum.
// ---------------------------------------------------------------------------
__global__ void stats16_kernel(const __half* __restrict__ a,
                               const __half* __restrict__ b,
                               __half* __restrict__ sum_out,
                               float* __restrict__ mean,
                               float* __restrict__ rstd) {
    const int row = blockIdx.x;
    const int tid = threadIdx.x;

    const float2 rawa = reinterpret_cast<const float2*>(a + (size_t)row * DD)[tid];
    __half2 a0 = *reinterpret_cast<const __half2*>(&rawa.x);
    __half2 a1 = *reinterpret_cast<const __half2*>(&rawa.y);
    float v0 = __half2float(__low2half(a0)),  v1 = __half2float(__high2half(a0));
    float v2 = __half2float(__low2half(a1)),  v3 = __half2float(__high2half(a1));

    if (b != nullptr) {
        const float2 rawb = reinterpret_cast<const float2*>(b + (size_t)row * DD)[tid];
        __half2 b0 = *reinterpret_cast<const __half2*>(&rawb.x);
        __half2 b1 = *reinterpret_cast<const __half2*>(&rawb.y);
        v0 += __half2float(__low2half(b0));  v1 += __half2float(__high2half(b0));
        v2 += __half2float(__low2half(b1));  v3 += __half2float(__high2half(b1));
        __half h0 = __float2half_rn(v0), h1 = __float2half_rn(v1);
        __half h2 = __float2half_rn(v2), h3 = __float2half_rn(v3);
        __half2* p = reinterpret_cast<__half2*>(sum_out + (size_t)row * DD);
        p[tid * 2]     = __halves2half2(h0, h1);
        p[tid * 2 + 1] = __halves2half2(h2, h3);
        v0 = __half2float(h0); v1 = __half2float(h1);
        v2 = __half2float(h2); v3 = __half2float(h3);
    }

    float s  = v0 + v1 + v2 + v3;
    float ss = v0 * v0 + v1 * v1 + v2 * v2 + v3 * v3;
    row_stats_finish(s, ss, row, mean, rstd, tid);
}

// ---------------------------------------------------------------------------
// Unified weight prep, all 3 layers in one launch. grid (64, 3), 256 threads.
// ---------------------------------------------------------------------------
__global__ __launch_bounds__(256)
void wprep_kernel(const float* __restrict__ W1, const float* __restrict__ W2,
                  const float* __restrict__ W3,
                  const float* __restrict__ g1, const float* __restrict__ g2,
                  const float* __restrict__ g3,
                  const float* __restrict__ b1, const float* __restrict__ b2,
                  const float* __restrict__ b3,
                  __half* __restrict__ wg,
                  float* __restrict__ Sp, float* __restrict__ Tp) {
    const int l = blockIdx.y;
    const float* W = (l == 0) ? W1 : (l == 1) ? W2 : W3;
    const float* g = (l == 0) ? g1 : (l == 1) ? g2 : g3;
    const float* b = (l == 0) ? b1 : (l == 1) ? b2 : b3;
    __half* wgo = wg + (size_t)l * DD * OO;
    float* Spo = Sp + (size_t)l * 64 * OO;
    float* Tpo = Tp + (size_t)l * 64 * OO;

    const int tid = threadIdx.x;
    const int k0 = blockIdx.x * 8;

    __shared__ float sw[8][513];
    for (int idx = tid; idx < 8 * 512; idx += 256) {
        const int kk = idx >> 9;
        const int n  = idx & 511;
        sw[kk][n] = W[(size_t)(k0 + kk) * OO + n];
    }
    __shared__ float sg[8], sb[8];
    if (tid < 8)            sg[tid] = g[k0 + tid];
    else if (tid < 16)      sb[tid - 8] = b[k0 + tid - 8];
    __syncthreads();

    #pragma unroll
    for (int half = 0; half < 2; half++) {
        const int n = tid + half * 256;
        float s = 0.f, t = 0.f;
        __align__(16) __half h[8];
        #pragma unroll
        for (int i = 0; i < 8; i++) {
            const float w = sw[i][n];
            const float gw = sg[i] * w;
            s += gw;
            t += sb[i] * w;
            h[i] = __float2half_rn(gw);
        }
        *reinterpret_cast<uint4*>(wgo + (size_t)n * DD + k0) =
            *reinterpret_cast<const uint4*>(h);
        Spo[blockIdx.x * OO + n] = s;
        Tpo[blockIdx.x * OO + n] = t;
    }
}

// ---------------------------------------------------------------------------
// S/T reduce, all layers: grid (2, 3) x 256 threads.
// ---------------------------------------------------------------------------
__global__ void str_kernel(const float* __restrict__ Sp,
                           const float* __restrict__ Tp,
                           float* __restrict__ S,
                           float* __restrict__ T) {
    const int l = blockIdx.y;
    const int n = blockIdx.x * 256 + threadIdx.x;
    const float* Spo = Sp + (size_t)l * 64 * OO;
    const float* Tpo = Tp + (size_t)l * 64 * OO;
    float s = 0.f, t = 0.f;
    #pragma unroll 8
    for (int i = 0; i < 64; i++) {
        s += Spo[i * OO + n];
        t += Tpo[i * OO + n];
    }
    S[l * OO + n] = s;
    T[l * OO + n] = t;
}

// ---------------------------------------------------------------------------
// fp16 HMMA GEMM with fused LN affine epilogue:
//   out = rstd[row] * (A@Wg^T - mean[row]*S[col]) + T[col]   (+tanh)
// CTA tile 128(M) x 256(N), BK=32, 3-stage cp.async, 8 warps (64x64 each).
// SMEM per stage (24KB): A at +0 (8KB), B at +8192 (16KB).
// Tile layout: rows x 64B, 16B chunks XOR-swizzled:
//   byte(row, k) = row*64 + (((k>>3) ^ (row&3)) & 3)*16 + (k&7)*2
// ---------------------------------------------------------------------------
template <bool TANH, typename OutT>
__global__ __launch_bounds__(256)
void gemm_ln_kernel(const __half* __restrict__ A,
                    const __half* __restrict__ B,
                    const float* __restrict__ mean,
                    const float* __restrict__ rstd,
                    const float* __restrict__ S,
                    const float* __restrict__ T,
                    OutT* __restrict__ C) {
    extern __shared__ char smem[];
    const uint32_t sb = smem_to_u32(smem);

    const int tid  = threadIdx.x;
    const int lane = tid & 31;
    const int wid  = tid >> 5;
    const int m0 = blockIdx.y * 128;
    const int n0 = blockIdx.x * 256;
    const int warp_m = (wid >> 2) * 64;   // 0, 64
    const int warp_n = (wid & 3) * 64;    // 0, 64, 128, 192

    float acc[4][8][4];
    #pragma unroll
    for (int i = 0; i < 4; i++)
        #pragma unroll
        for (int j = 0; j < 8; j++)
            #pragma unroll
            for (int q = 0; q < 4; q++) acc[i][j][q] = 0.0f;

    // --- ldmatrix per-lane base addressing ---
    const int arow  = warp_m + (lane & 7) + ((lane >> 3) & 1) * 8;   // + mt*16
    const int akblk = (lane >> 4) & 1;
    const int ax    = arow & 3;
    const int brow  = warp_n + (lane & 7) + ((lane >> 4) & 1) * 8;   // + jj*16
    const int bkblk = (lane >> 3) & 1;
    const int bx    = brow & 3;

    #define AOFF(mt, kb) \
        (uint32_t)((arow + (mt) * 16) * 64 + (((((kb) >> 3) + akblk) ^ ax) & 3) * 16)
    #define BOFF(jj, kb) \
        (uint32_t)((brow + (jj) * 16) * 64 + (((((kb) >> 3) + bkblk) ^ bx) & 3) * 16)

    // --- cp.async stage load: A 2x16B, B 4x16B per thread ---
    const int lrow = tid >> 2;        // 0..63
    const int lch  = tid & 3;         // 16B chunk within 64B row
    uint32_t dA[2], dB[4];
    size_t gA[2], gB[4];
    #pragma unroll
    for (int i = 0; i < 2; i++) {
        const int r = lrow + 64 * i;
        dA[i] = (uint32_t)(r * 64 + ((lch ^ (r & 3)) << 4));
        gA[i] = (size_t)(m0 + r) * DD + lch * 8;
    }
    #pragma unroll
    for (int i = 0; i < 4; i++) {
        const int r = lrow + 64 * i;
        dB[i] = (uint32_t)(r * 64 + ((lch ^ (r & 3)) << 4));
        gB[i] = (size_t)(n0 + r) * DD + lch * 8;
    }

    #define LOAD_STAGE(it, st) do {                                      \
        const int _k0 = (it) * 32;                                       \
        const uint32_t _sa = sb + (uint32_t)(st) * 24576u;               \
        const uint32_t _sbb = _sa + 8192u;                               \
        cp16(_sa + dA[0], A + gA[0] + _k0);                              \
        cp16(_sa + dA[1], A + gA[1] + _k0);                              \
        cp16(_sbb + dB[0], B + gB[0] + _k0);                             \
        cp16(_sbb + dB[1], B + gB[1] + _k0);                             \
        cp16(_sbb + dB[2], B + gB[2] + _k0);                             \
        cp16(_sbb + dB[3], B + gB[3] + _k0);                             \
        asm volatile("cp.async.commit_group;" ::: "memory");             \
    } while (0)

    LOAD_STAGE(0, 0);
    LOAD_STAGE(1, 1);

    const int NK = DD / 32;   // 16
    int st = 0;
    for (int it = 0; it < NK; it++) {
        if (it + 1 < NK) {
            asm volatile("cp.async.wait_group 1;" ::: "memory");
        } else {
            asm volatile("cp.async.wait_group 0;" ::: "memory");
        }
        __syncthreads();

        if (it + 2 < NK) {
            int st2 = st + 2; if (st2 >= 3) st2 -= 3;
            LOAD_STAGE(it + 2, st2);
        }

        const uint32_t sa  = sb + (uint32_t)st * 24576u;
        const uint32_t sbB = sa + 8192u;
        #pragma unroll
        for (int ks = 0; ks < 2; ks++) {
            const int kb = ks * 16;
            uint32_t af[4][4];
            #pragma unroll
            for (int mt = 0; mt < 4; mt++)
                ldm_x4(af[mt], sa + AOFF(mt, kb));
            uint32_t bf[4][4];
            #pragma unroll
            for (int jj = 0; jj < 4; jj++)
                ldm_x4(bf[jj], sbB + BOFF(jj, kb));
            #pragma unroll
            for (int mt = 0; mt < 4; mt++) {
                #pragma unroll
                for (int j = 0; j < 8; j++) {
                    const int jj = j >> 1, jh = (j & 1) * 2;
                    mma_fp16(acc[mt][j], af[mt], bf[jj][jh], bf[jj][jh + 1]);
                }
            }
        }
        if (++st >= 3) st = 0;
    }
    #undef LOAD_STAGE
    #undef AOFF
    #undef BOFF

    // Epilogue: fused LN affine (+tanh), write OutT
    #pragma unroll
    for (int mt = 0; mt < 4; mt++) {
        const int r0 = m0 + warp_m + mt * 16 + (lane >> 2);
        const int r1 = r0 + 8;
        const float mn0 = mean[r0], rs0 = rstd[r0];
        const float mn1 = mean[r1], rs1 = rstd[r1];
        #pragma unroll
        for (int j = 0; j < 8; j++) {
            const int col = n0 + warp_n + j * 8 + (lane & 3) * 2;
            const float s0 = S[col], s1 = S[col + 1];
            const float t0 = T[col], t1 = T[col + 1];
            float v0 = rs0 * (acc[mt][j][0] - mn0 * s0) + t0;
            float v1 = rs0 * (acc[mt][j][1] - mn0 * s1) + t1;
            float v2 = rs1 * (acc[mt][j][2] - mn1 * s0) + t0;
            float v3 = rs1 * (acc[mt][j][3] - mn1 * s1) + t1;
            if (TANH) { v0 = tanhf(v0); v1 = tanhf(v1); v2 = tanhf(v2); v3 = tanhf(v3); }
            if (sizeof(OutT) == 2) {
                __half2* p0 = reinterpret_cast<__half2*>((__half*)C + (size_t)r0 * OO + col);
                __half2* p1 = reinterpret_cast<__half2*>((__half*)C + (size_t)r1 * OO + col);
                *p0 = __halves2half2(__float2half_rn(v0), __float2half_rn(v1));
                *p1 = __halves2half2(__float2half_rn(v2), __float2half_rn(v3));
            } else {
                *reinterpret_cast<float2*>((float*)C + (size_t)r0 * OO + col) = make_float2(v0, v1);
                *reinterpret_cast<float2*>((float*)C + (size_t)r1 * OO + col) = make_float2(v2, v3);
            }
        }
    }
}

// ---------------------------------------------------------------------------
// SMEM-resident masked softmax over axis=1 (N=256), in-place on out[B,N,O].
// grid (BB, 8), 256 threads; 256n x 64o panel in 64KB dynamic SMEM.
// ---------------------------------------------------------------------------
__global__ __launch_bounds__(256)
void softmax_kernel(float* __restrict__ out, const unsigned* __restrict__ mask) {
    extern __shared__ float sv[];   // [256][64]
    __shared__ unsigned smask[NN];
    __shared__ float red_m[4][64], red_s[4][64];

    const int b  = blockIdx.x;
    const int o0 = blockIdx.y * 64;
    const int tid = threadIdx.x;

    smask[tid] = mask[(size_t)b * NN + tid];
    __syncthreads();
    int any = __syncthreads_or(smask[tid] != 0u);
    if (!any && tid == 0) smask[0] = 1u;
    __syncthreads();

    float* base = out + (size_t)b * NN * OO + o0;

    for (int idx = tid; idx < NN * 64; idx += 256) {
        const int n = idx >> 6, c = idx & 63;
        sv[idx] = base[(size_t)n * OO + c];
    }
    __syncthreads();

    const int col = tid & 63;
    const int seg = tid >> 6;
    float m = -INFINITY, s = 0.0f;
    for (int n = seg * 64; n < seg * 64 + 64; n++) {
        if (smask[n]) {
            const float v = sv[n * 64 + col];
            const float nm = fmaxf(m, v);
            s = s * __expf(m - nm) + __expf(v - nm);
            m = nm;
        }
    }
    red_m[seg][col] = m;
    red_s[seg][col] = s;
    __syncthreads();

    if (seg == 0) {
        float M = red_m[0][col];
        #pragma unroll
        for (int i = 1; i < 4; i++) M = fmaxf(M, red_m[i][col]);
        float SS = 0.0f;
        #pragma unroll
        for (int i = 0; i < 4; i++) {
            const float mi = red_m[i][col];
            if (mi != -INFINITY) SS += red_s[i][col] * __expf(mi - M);
        }
        red_m[0][col] = M;
        red_s[0][col] = 1.0f / SS;
    }
    __syncthreads();

    const float M  = red_m[0][col];
    const float rs = red_s[0][col];
    for (int n = seg * 64; n < seg * 64 + 64; n++) {
        const float v = smask[n] ? __expf(sv[n * 64 + col] - M) * rs : 0.0f;
        sv[n * 64 + col] = v;
    }
    __syncthreads();

    for (int idx = tid; idx < NN * 64; idx += 256) {
        const int n = idx >> 6, c = idx & 63;
        base[(size_t)n * OO + c] = sv[idx];
    }
}

// ---------------------------------------------------------------------------
// Launch
// ---------------------------------------------------------------------------
extern "C" void kernel_launch(void* const* d_in, const int* in_sizes, int n_in,
                              void* d_out, int out_size) {
    const float*    Obs  = (const float*)d_in[0];
    const unsigned* mask = (const unsigned*)d_in[1];
    const float* g1 = (const float*)d_in[2];
    const float* b1 = (const float*)d_in[3];
    const float* W1 = (const float*)d_in[4];
    const float* g2 = (const float*)d_in[5];
    const float* b2 = (const float*)d_in[6];
    const float* W2 = (const float*)d_in[7];
    const float* g3 = (const float*)d_in[8];
    const float* b3 = (const float*)d_in[9];
    const float* W3 = (const float*)d_in[10];
    float* out = (float*)d_out;

    __half *x16, *h1, *h2, *wg;
    float *mean, *rstd, *S, *T, *Sp, *Tp;
    cudaGetSymbolAddress((void**)&x16, g_x16);
    cudaGetSymbolAddress((void**)&h1, g_h1);
    cudaGetSymbolAddress((void**)&h2, g_h2);
    cudaGetSymbolAddress((void**)&wg, g_wg);
    cudaGetSymbolAddress((void**)&mean, g_mean);
    cudaGetSymbolAddress((void**)&rstd, g_rstd);
    cudaGetSymbolAddress((void**)&S, g_S);
    cudaGetSymbolAddress((void**)&T, g_T);
    cudaGetSymbolAddress((void**)&Sp, g_Sp);
    cudaGetSymbolAddress((void**)&Tp, g_Tp);

    static bool attr_done = false;
    const int DSMEM = 3 * 24576;        // 73728: 3 stages x 24KB
    const int SMEM_SOFT = NN * 64 * 4;  // 64KB
    if (!attr_done) {
        cudaFuncSetAttribute(gemm_ln_kernel<true, __half>,
                             cudaFuncAttributeMaxDynamicSharedMemorySize, DSMEM);
        cudaFuncSetAttribute(gemm_ln_kernel<false, float>,
                             cudaFuncAttributeMaxDynamicSharedMemorySize, DSMEM);
        cudaFuncSetAttribute(softmax_kernel,
                             cudaFuncAttributeMaxDynamicSharedMemorySize, SMEM_SOFT);
        attr_done = true;
    }

    const dim3 gGemm(OO / 256, MROWS / 128);   // (2, 256)

    // All weight prep up-front (depends only on inputs)
    wprep_kernel<<<dim3(64, 3), 256>>>(W1, W2, W3, g1, g2, g3, b1, b2, b3,
                                       wg, Sp, Tp);
    str_kernel<<<dim3(2, 3), 256>>>(Sp, Tp, S, T);

    // Block 1
    stats32_kernel<<<MROWS, 128>>>(Obs, x16, mean, rstd);
    gemm_ln_kernel<true, __half><<<gGemm, 256, DSMEM>>>(
        x16, wg, mean, rstd, S, T, h1);

    // Block 2
    stats16_kernel<<<MROWS, 128>>>(h1, nullptr, nullptr, mean, rstd);
    gemm_ln_kernel<true, __half><<<gGemm, 256, DSMEM>>>(
        h1, wg + (size_t)DD * OO, mean, rstd, S + OO, T + OO, h2);

    // Block 3 (residual h1+h2, no activation, fp32 out)
    stats16_kernel<<<MROWS, 128>>>(h1, h2, x16, mean, rstd);
    gemm_ln_kernel<false, float><<<gGemm, 256, DSMEM>>>(
        x16, wg + 2 * (size_t)DD * OO, mean, rstd, S + 2 * OO, T + 2 * OO, out);

    // Masked softmax over axis=1, in place
    softmax_kernel<<<dim3(BB, 8), 256, SMEM_SOFT>>>(out, mask);
}

// round 12
// speedup vs baseline: 1.1451x; 1.1451x over previous
#include <cuda_runtime.h>
#include <cuda_fp16.h>
#include <math.h>
#include <stdint.h>

#define BB 128
#define NN 256
#define DD 512
#define OO 512
#define MROWS (BB * NN)   // 32768

// ---------------------------------------------------------------------------
// Scratch (no cudaMalloc allowed)
// ---------------------------------------------------------------------------
__device__ __half g_x16[(size_t)MROWS * DD];   // block1: fp16(Obs); later: fp16(h1+h2)
__device__ __half g_h1[(size_t)MROWS * OO];    // fp16 GEMM1 output
__device__ __half g_wg[3 * (size_t)DD * OO];   // (g∘W)^T per layer: [N][K] fp16
__device__ float  g_mean[MROWS];
__device__ float  g_rstd[MROWS];
__device__ float  g_S[3 * OO];
__device__ float  g_T[3 * OO];
__device__ float  g_Sp[3 * 64 * OO];
__device__ float  g_Tp[3 * 64 * OO];
__device__ float  g_ps[(size_t)MROWS * 8];     // per-row sum partials (8 col-chunks)
__device__ float  g_pq[(size_t)MROWS * 8];     // per-row sumsq partials

// ---------------------------------------------------------------------------
// Helpers (sm_80-era PTX only — must assemble under compute_103)
// ---------------------------------------------------------------------------
__device__ __forceinline__ uint32_t smem_to_u32(const void* p) {
    uint32_t a;
    asm("{ .reg .u64 t; cvta.to.shared.u64 t, %1; cvt.u32.u64 %0, t; }"
        : "=r"(a) : "l"(p));
    return a;
}
__device__ __forceinline__ void cp16(uint32_t dst, const void* src) {
    asm volatile("cp.async.cg.shared.global [%0], [%1], 16;"
                 :: "r"(dst), "l"(src) : "memory");
}
__device__ __forceinline__ void ldm_x4(uint32_t* r, uint32_t addr) {
    asm volatile("ldmatrix.sync.aligned.m8n8.x4.shared.b16 {%0,%1,%2,%3}, [%4];"
                 : "=r"(r[0]), "=r"(r[1]), "=r"(r[2]), "=r"(r[3]) : "r"(addr));
}
__device__ __forceinline__ void mma_fp16(float* c, const uint32_t* a,
                                         uint32_t b0, uint32_t b1) {
    asm volatile(
        "mma.sync.aligned.m16n8k16.row.col.f32.f16.f16.f32 "
        "{%0,%1,%2,%3}, {%4,%5,%6,%7}, {%8,%9}, {%0,%1,%2,%3};"
        : "+f"(c[0]), "+f"(c[1]), "+f"(c[2]), "+f"(c[3])
        : "r"(a[0]), "r"(a[1]), "r"(a[2]), "r"(a[3]), "r"(b0), "r"(b1));
}

// Block-wide (128 threads) mean/rstd reduction.
__device__ __forceinline__ void row_stats_finish(float s, float ss, int row,
                                                 float* mean, float* rstd, int tid) {
    #pragma unroll
    for (int o = 16; o > 0; o >>= 1) {
        s  += __shfl_xor_sync(0xFFFFFFFFu, s,  o);
        ss += __shfl_xor_sync(0xFFFFFFFFu, ss, o);
    }
    __shared__ float sh_s[4], sh_ss[4];
    const int w = tid >> 5;
    if ((tid & 31) == 0) { sh_s[w] = s; sh_ss[w] = ss; }
    __syncthreads();
    if (tid == 0) {
        s  = sh_s[0] + sh_s[1] + sh_s[2] + sh_s[3];
        ss = sh_ss[0] + sh_ss[1] + sh_ss[2] + sh_ss[3];
        const float mn  = s * (1.0f / DD);
        const float var = ss * (1.0f / DD) - mn * mn;
        mean[row] = mn;
        rstd[row] = rsqrtf(var + 1e-5f);
    }
}

// ---------------------------------------------------------------------------
// Block 1 stats: read fp32 x, write fp16(x) + row mean/rstd (stats from fp32).
// ---------------------------------------------------------------------------
__global__ void stats32_kernel(const float* __restrict__ x,
                               __half* __restrict__ x16,
                               float* __restrict__ mean,
                               float* __restrict__ rstd) {
    const int row = blockIdx.x;
    const int tid = threadIdx.x;
    float4 v = reinterpret_cast<const float4*>(x + (size_t)row * DD)[tid];

    __half2* p = reinterpret_cast<__half2*>(x16 + (size_t)row * DD);
    p[tid * 2]     = __halves2half2(__float2half_rn(v.x), __float2half_rn(v.y));
    p[tid * 2 + 1] = __halves2half2(__float2half_rn(v.z), __float2half_rn(v.w));

    float s  = v.x + v.y + v.z + v.w;
    float ss = v.x * v.x + v.y * v.y + v.z * v.z + v.w * v.w;
    row_stats_finish(s, ss, row, mean, rstd, tid);
}

// ---------------------------------------------------------------------------
// Finalize row stats from per-chunk partials. grid 128 x 256 threads.
// ---------------------------------------------------------------------------
__global__ void finalize_kernel(const float* __restrict__ ps,
                                const float* __restrict__ pq,
                                float* __restrict__ mean,
                                float* __restrict__ rstd) {
    const int row = blockIdx.x * 256 + threadIdx.x;
    float s = 0.f, q = 0.f;
    #pragma unroll
    for (int i = 0; i < 8; i++) {
        s += ps[(size_t)row * 8 + i];
        q += pq[(size_t)row * 8 + i];
    }
    const float mn  = s * (1.0f / DD);
    const float var = q * (1.0f / DD) - mn * mn;
    mean[row] = mn;
    rstd[row] = rsqrtf(var + 1e-5f);
}

// ---------------------------------------------------------------------------
// Unified weight prep, all 3 layers in one launch. grid (64, 3), 256 threads.
// ---------------------------------------------------------------------------
__global__ __launch_bounds__(256)
void wprep_kernel(const float* __restrict__ W1, const float* __restrict__ W2,
                  const float* __restrict__ W3,
                  const float* __restrict__ g1, const float* __restrict__ g2,
                  const float* __restrict__ g3,
                  const float* __restrict__ b1, const float* __restrict__ b2,
                  const float* __restrict__ b3,
                  __half* __restrict__ wg,
                  float* __restrict__ Sp, float* __restrict__ Tp) {
    const int l = blockIdx.y;
    const float* W = (l == 0) ? W1 : (l == 1) ? W2 : W3;
    const float* g = (l == 0) ? g1 : (l == 1) ? g2 : g3;
    const float* b = (l == 0) ? b1 : (l == 1) ? b2 : b3;
    __half* wgo = wg + (size_t)l * DD * OO;
    float* Spo = Sp + (size_t)l * 64 * OO;
    float* Tpo = Tp + (size_t)l * 64 * OO;

    const int tid = threadIdx.x;
    const int k0 = blockIdx.x * 8;

    __shared__ float sw[8][513];
    for (int idx = tid; idx < 8 * 512; idx += 256) {
        const int kk = idx >> 9;
        const int n  = idx & 511;
        sw[kk][n] = W[(size_t)(k0 + kk) * OO + n];
    }
    __shared__ float sg[8], sb[8];
    if (tid < 8)            sg[tid] = g[k0 + tid];
    else if (tid < 16)      sb[tid - 8] = b[k0 + tid - 8];
    __syncthreads();

    #pragma unroll
    for (int half = 0; half < 2; half++) {
        const int n = tid + half * 256;
        float s = 0.f, t = 0.f;
        __align__(16) __half h[8];
        #pragma unroll
        for (int i = 0; i < 8; i++) {
            const float w = sw[i][n];
            const float gw = sg[i] * w;
            s += gw;
            t += sb[i] * w;
            h[i] = __float2half_rn(gw);
        }
        *reinterpret_cast<uint4*>(wgo + (size_t)n * DD + k0) =
            *reinterpret_cast<const uint4*>(h);
        Spo[blockIdx.x * OO + n] = s;
        Tpo[blockIdx.x * OO + n] = t;
    }
}

// ---------------------------------------------------------------------------
// S/T reduce, all layers: grid (2, 3) x 256 threads.
// ---------------------------------------------------------------------------
__global__ void str_kernel(const float* __restrict__ Sp,
                           const float* __restrict__ Tp,
                           float* __restrict__ S,
                           float* __restrict__ T) {
    const int l = blockIdx.y;
    const int n = blockIdx.x * 256 + threadIdx.x;
    const float* Spo = Sp + (size_t)l * 64 * OO;
    const float* Tpo = Tp + (size_t)l * 64 * OO;
    float s = 0.f, t = 0.f;
    #pragma unroll 8
    for (int i = 0; i < 64; i++) {
        s += Spo[i * OO + n];
        t += Tpo[i * OO + n];
    }
    S[l * OO + n] = s;
    T[l * OO + n] = t;
}

// ---------------------------------------------------------------------------
// fp16 HMMA GEMM with fused LN affine epilogue (+optional residual add and
// per-row stats partials for the NEXT layer's LN):
//   val = rstd[row]*(A@Wg^T - mean[row]*S[col]) + T[col]; TANH: val=tanh(val)
//   RESID: val += resid[row,col] (loaded fp16); out = fp16/fp32(val)
//   STATS: per-(row, 64col-chunk) sum/sumsq of rounded outputs -> ps/pq
// CTA 128x128, warp 32x64, BK=32, 3-stage cp.async, 2 CTAs/SM.
// ---------------------------------------------------------------------------
template <bool TANH, bool STATS, bool RESID, typename OutT>
__global__ __launch_bounds__(256, 2)
void gemm_ln_kernel(const __half* __restrict__ A,
                    const __half* __restrict__ B,
                    const float* __restrict__ mean,
                    const float* __restrict__ rstd,
                    const float* __restrict__ S,
                    const float* __restrict__ T,
                    const __half* __restrict__ resid,
                    float* __restrict__ ps,
                    float* __restrict__ pq,
                    OutT* __restrict__ C) {
    extern __shared__ char smem[];
    const uint32_t sb = smem_to_u32(smem);

    const int tid  = threadIdx.x;
    const int lane = tid & 31;
    const int wid  = tid >> 5;
    const int m0 = blockIdx.y * 128;
    const int n0 = blockIdx.x * 128;
    const int warp_m = (wid >> 1) * 32;
    const int warp_n = (wid & 1) * 64;

    float acc[2][8][4];
    #pragma unroll
    for (int i = 0; i < 2; i++)
        #pragma unroll
        for (int j = 0; j < 8; j++)
            #pragma unroll
            for (int q = 0; q < 4; q++) acc[i][j][q] = 0.0f;

    const int arow  = warp_m + (lane & 7) + ((lane >> 3) & 1) * 8;
    const int akblk = (lane >> 4) & 1;
    const int ax    = arow & 3;
    const int brow  = warp_n + (lane & 7) + ((lane >> 4) & 1) * 8;
    const int bkblk = (lane >> 3) & 1;
    const int bx    = brow & 3;

    #define AOFF(mt, kb) \
        (uint32_t)((arow + (mt) * 16) * 64 + (((((kb) >> 3) + akblk) ^ ax) & 3) * 16)
    #define BOFF(jj, kb) \
        (uint32_t)((brow + (jj) * 16) * 64 + (((((kb) >> 3) + bkblk) ^ bx) & 3) * 16)

    const int c0row = tid >> 2,          c0ch = tid & 3;
    const int c1row = (tid + 256) >> 2;
    const uint32_t d0 = (uint32_t)(c0row * 64 + ((c0ch ^ (c0row & 3)) << 4));
    const uint32_t d1 = (uint32_t)(c1row * 64 + ((c0ch ^ (c1row & 3)) << 4));
    const size_t gA0 = (size_t)(m0 + c0row) * DD + c0ch * 8;
    const size_t gA1 = (size_t)(m0 + c1row) * DD + c0ch * 8;
    const size_t gB0 = (size_t)(n0 + c0row) * DD + c0ch * 8;
    const size_t gB1 = (size_t)(n0 + c1row) * DD + c0ch * 8;

    #define LOAD_STAGE(it, st) do {                                      \
        const int _k0 = (it) * 32;                                       \
        const uint32_t _sa = sb + (uint32_t)(st) * 16384u;               \
        const uint32_t _sbb = _sa + 8192u;                               \
        cp16(_sa + d0, A + gA0 + _k0);                                   \
        cp16(_sa + d1, A + gA1 + _k0);                                   \
        cp16(_sbb + d0, B + gB0 + _k0);                                  \
        cp16(_sbb + d1, B + gB1 + _k0);                                  \
        asm volatile("cp.async.commit_group;" ::: "memory");             \
    } while (0)

    LOAD_STAGE(0, 0);
    LOAD_STAGE(1, 1);

    const int NK = DD / 32;   // 16
    int st = 0;
    for (int it = 0; it < NK; it++) {
        if (it + 1 < NK) {
            asm volatile("cp.async.wait_group 1;" ::: "memory");
        } else {
            asm volatile("cp.async.wait_group 0;" ::: "memory");
        }
        __syncthreads();

        if (it + 2 < NK) {
            int st2 = st + 2; if (st2 >= 3) st2 -= 3;
            LOAD_STAGE(it + 2, st2);
        }

        const uint32_t sa  = sb + (uint32_t)st * 16384u;
        const uint32_t sbB = sa + 8192u;
        #pragma unroll
        for (int ks = 0; ks < 2; ks++) {
            const int kb = ks * 16;
            uint32_t af[2][4];
            #pragma unroll
            for (int mt = 0; mt < 2; mt++)
                ldm_x4(af[mt], sa + AOFF(mt, kb));
            uint32_t bf[4][4];
            #pragma unroll
            for (int jj = 0; jj < 4; jj++)
                ldm_x4(bf[jj], sbB + BOFF(jj, kb));
            #pragma unroll
            for (int j = 0; j < 8; j++) {
                const int jj = j >> 1, jh = (j & 1) * 2;
                const uint32_t b0 = bf[jj][jh], b1 = bf[jj][jh + 1];
                #pragma unroll
                for (int mt = 0; mt < 2; mt++)
                    mma_fp16(acc[mt][j], af[mt], b0, b1);
            }
        }
        if (++st >= 3) st = 0;
    }
    #undef LOAD_STAGE
    #undef AOFF
    #undef BOFF

    // Epilogue: fused LN affine (+tanh) (+residual) (+stats partials)
    #pragma unroll
    for (int mt = 0; mt < 2; mt++) {
        const int r0 = m0 + warp_m + mt * 16 + (lane >> 2);
        const int r1 = r0 + 8;
        const float mn0 = mean[r0], rs0 = rstd[r0];
        const float mn1 = mean[r1], rs1 = rstd[r1];
        float s0 = 0.f, q0 = 0.f, s1 = 0.f, q1 = 0.f;
        #pragma unroll
        for (int j = 0; j < 8; j++) {
            const int col = n0 + warp_n + j * 8 + (lane & 3) * 2;
            const float sc0 = S[col], sc1 = S[col + 1];
            const float tc0 = T[col], tc1 = T[col + 1];
            float v0 = rs0 * (acc[mt][j][0] - mn0 * sc0) + tc0;
            float v1 = rs0 * (acc[mt][j][1] - mn0 * sc1) + tc1;
            float v2 = rs1 * (acc[mt][j][2] - mn1 * sc0) + tc0;
            float v3 = rs1 * (acc[mt][j][3] - mn1 * sc1) + tc1;
            if (TANH) { v0 = tanhf(v0); v1 = tanhf(v1); v2 = tanhf(v2); v3 = tanhf(v3); }
            if (RESID) {
                const __half2 h2a = *reinterpret_cast<const __half2*>(
                    resid + (size_t)r0 * OO + col);
                const __half2 h2b = *reinterpret_cast<const __half2*>(
                    resid + (size_t)r1 * OO + col);
                v0 += __half2float(__low2half(h2a));
                v1 += __half2float(__high2half(h2a));
                v2 += __half2float(__low2half(h2b));
                v3 += __half2float(__high2half(h2b));
            }
            if (sizeof(OutT) == 2) {
                const __half h0 = __float2half_rn(v0), h1 = __float2half_rn(v1);
                const __half h2 = __float2half_rn(v2), h3 = __float2half_rn(v3);
                *reinterpret_cast<__half2*>((__half*)C + (size_t)r0 * OO + col) =
                    __halves2half2(h0, h1);
                *reinterpret_cast<__half2*>((__half*)C + (size_t)r1 * OO + col) =
                    __halves2half2(h2, h3);
                if (STATS) {
                    const float f0 = __half2float(h0), f1 = __half2float(h1);
                    const float f2 = __half2float(h2), f3 = __half2float(h3);
                    s0 += f0 + f1; q0 += f0 * f0 + f1 * f1;
                    s1 += f2 + f3; q1 += f2 * f2 + f3 * f3;
                }
            } else {
                *reinterpret_cast<float2*>((float*)C + (size_t)r0 * OO + col) =
                    make_float2(v0, v1);
                *reinterpret_cast<float2*>((float*)C + (size_t)r1 * OO + col) =
                    make_float2(v2, v3);
            }
        }
        if (STATS) {
            #pragma unroll
            for (int o = 1; o <= 2; o <<= 1) {
                s0 += __shfl_xor_sync(0xFFFFFFFFu, s0, o);
                q0 += __shfl_xor_sync(0xFFFFFFFFu, q0, o);
                s1 += __shfl_xor_sync(0xFFFFFFFFu, s1, o);
                q1 += __shfl_xor_sync(0xFFFFFFFFu, q1, o);
            }
            if ((lane & 3) == 0) {
                const int chunk = blockIdx.x * 2 + (wid & 1);
                ps[(size_t)r0 * 8 + chunk] = s0;
                pq[(size_t)r0 * 8 + chunk] = q0;
                ps[(size_t)r1 * 8 + chunk] = s1;
                pq[(size_t)r1 * 8 + chunk] = q1;
            }
        }
    }
}

// ---------------------------------------------------------------------------
// SMEM-resident masked softmax over axis=1 (N=256), in-place on out[B,N,O].
// grid (BB, 8), 256 threads; 256n x 64o panel in 64KB dynamic SMEM.
// ---------------------------------------------------------------------------
__global__ __launch_bounds__(256)
void softmax_kernel(float* __restrict__ out, const unsigned* __restrict__ mask) {
    extern __shared__ float sv[];   // [256][64]
    __shared__ unsigned smask[NN];
    __shared__ float red_m[4][64], red_s[4][64];

    const int b  = blockIdx.x;
    const int o0 = blockIdx.y * 64;
    const int tid = threadIdx.x;

    smask[tid] = mask[(size_t)b * NN + tid];
    __syncthreads();
    int any = __syncthreads_or(smask[tid] != 0u);
    if (!any && tid == 0) smask[0] = 1u;
    __syncthreads();

    float* base = out + (size_t)b * NN * OO + o0;

    for (int idx = tid; idx < NN * 64; idx += 256) {
        const int n = idx >> 6, c = idx & 63;
        sv[idx] = base[(size_t)n * OO + c];
    }
    __syncthreads();

    const int col = tid & 63;
    const int seg = tid >> 6;
    float m = -INFINITY, s = 0.0f;
    for (int n = seg * 64; n < seg * 64 + 64; n++) {
        if (smask[n]) {
            const float v = sv[n * 64 + col];
            const float nm = fmaxf(m, v);
            s = s * __expf(m - nm) + __expf(v - nm);
            m = nm;
        }
    }
    red_m[seg][col] = m;
    red_s[seg][col] = s;
    __syncthreads();

    if (seg == 0) {
        float M = red_m[0][col];
        #pragma unroll
        for (int i = 1; i < 4; i++) M = fmaxf(M, red_m[i][col]);
        float SS = 0.0f;
        #pragma unroll
        for (int i = 0; i < 4; i++) {
            const float mi = red_m[i][col];
            if (mi != -INFINITY) SS += red_s[i][col] * __expf(mi - M);
        }
        red_m[0][col] = M;
        red_s[0][col] = 1.0f / SS;
    }
    __syncthreads();

    const float M  = red_m[0][col];
    const float rs = red_s[0][col];
    for (int n = seg * 64; n < seg * 64 + 64; n++) {
        const float v = smask[n] ? __expf(sv[n * 64 + col] - M) * rs : 0.0f;
        sv[n * 64 + col] = v;
    }
    __syncthreads();

    for (int idx = tid; idx < NN * 64; idx += 256) {
        const int n = idx >> 6, c = idx & 63;
        base[(size_t)n * OO + c] = sv[idx];
    }
}

// ---------------------------------------------------------------------------
// Launch
// ---------------------------------------------------------------------------
extern "C" void kernel_launch(void* const* d_in, const int* in_sizes, int n_in,
                              void* d_out, int out_size) {
    const float*    Obs  = (const float*)d_in[0];
    const unsigned* mask = (const unsigned*)d_in[1];
    const float* g1 = (const float*)d_in[2];
    const float* b1 = (const float*)d_in[3];
    const float* W1 = (const float*)d_in[4];
    const float* g2 = (const float*)d_in[5];
    const float* b2 = (const float*)d_in[6];
    const float* W2 = (const float*)d_in[7];
    const float* g3 = (const float*)d_in[8];
    const float* b3 = (const float*)d_in[9];
    const float* W3 = (const float*)d_in[10];
    float* out = (float*)d_out;

    __half *x16, *h1, *wg;
    float *mean, *rstd, *S, *T, *Sp, *Tp, *ps, *pq;
    cudaGetSymbolAddress((void**)&x16, g_x16);
    cudaGetSymbolAddress((void**)&h1, g_h1);
    cudaGetSymbolAddress((void**)&wg, g_wg);
    cudaGetSymbolAddress((void**)&mean, g_mean);
    cudaGetSymbolAddress((void**)&rstd, g_rstd);
    cudaGetSymbolAddress((void**)&S, g_S);
    cudaGetSymbolAddress((void**)&T, g_T);
    cudaGetSymbolAddress((void**)&Sp, g_Sp);
    cudaGetSymbolAddress((void**)&Tp, g_Tp);
    cudaGetSymbolAddress((void**)&ps, g_ps);
    cudaGetSymbolAddress((void**)&pq, g_pq);

    static bool attr_done = false;
    const int DSMEM = 49152;            // 3 stages x 16KB
    const int SMEM_SOFT = NN * 64 * 4;  // 64KB
    if (!attr_done) {
        cudaFuncSetAttribute((const void*)gemm_ln_kernel<true, true, false, __half>,
                             cudaFuncAttributeMaxDynamicSharedMemorySize, DSMEM);
        cudaFuncSetAttribute((const void*)gemm_ln_kernel<true, true, true, __half>,
                             cudaFuncAttributeMaxDynamicSharedMemorySize, DSMEM);
        cudaFuncSetAttribute((const void*)gemm_ln_kernel<false, false, false, float>,
                             cudaFuncAttributeMaxDynamicSharedMemorySize, DSMEM);
        cudaFuncSetAttribute((const void*)softmax_kernel,
                             cudaFuncAttributeMaxDynamicSharedMemorySize, SMEM_SOFT);
        attr_done = true;
    }

    const dim3 gGemm(OO / 128, MROWS / 128);   // (4, 256)

    // Weight prep up-front (depends only on inputs)
    wprep_kernel<<<dim3(64, 3), 256>>>(W1, W2, W3, g1, g2, g3, b1, b2, b3,
                                       wg, Sp, Tp);
    str_kernel<<<dim3(2, 3), 256>>>(Sp, Tp, S, T);

    // Block 1: stats(Obs)+convert; GEMM1 -> h1 (fp16) + stats partials of h1
    stats32_kernel<<<MROWS, 128>>>(Obs, x16, mean, rstd);
    gemm_ln_kernel<true, true, false, __half><<<gGemm, 256, DSMEM>>>(
        x16, wg, mean, rstd, S, T, nullptr, ps, pq, h1);
    finalize_kernel<<<MROWS / 256, 256>>>(ps, pq, mean, rstd);

    // Block 2: GEMM2 -> x16 = fp16(h1 + tanh(...)) + stats partials
    gemm_ln_kernel<true, true, true, __half><<<gGemm, 256, DSMEM>>>(
        h1, wg + (size_t)DD * OO, mean, rstd, S + OO, T + OO, h1, ps, pq, x16);
    finalize_kernel<<<MROWS / 256, 256>>>(ps, pq, mean, rstd);

    // Block 3: GEMM3 -> out (fp32), no stats
    gemm_ln_kernel<false, false, false, float><<<gGemm, 256, DSMEM>>>(
        x16, wg + 2 * (size_t)DD * OO, mean, rstd, S + 2 * OO, T + 2 * OO,
        nullptr, nullptr, nullptr, out);

    // Masked softmax over axis=1, in place
    softmax_kernel<<<dim3(BB, 8), 256, SMEM_SOFT>>>(out, mask);
}